// round 1
// baseline (speedup 1.0000x reference)
#include <cuda_runtime.h>
#include <math.h>

#define BB 4
#define NN 2048
#define MM 16
#define SS 200

// ---------------- device scratch (no allocations allowed) ----------------
__device__ float  g_R[BB * MM * 9];
__device__ float4 g_pts[BB * MM * SS];   // deformed, gathered sample points (w unused)
__device__ float  g_area[BB * MM];       // raw (unnormalized) areas
__device__ float  g_d2sum[BB * MM];      // sum over S of min_n dist
__device__ double g_p2p;                 // pcl_to_prim accumulator
__device__ double g_emb;                 // emb_reg scalar

__device__ __forceinline__ float fexp_f(float x, float p) {
    float s = (x > 0.f) ? 1.f : ((x < 0.f) ? -1.f : 0.f);
    return s * powf(fabsf(x) + 1e-6f, p);
}

__device__ __forceinline__ double blockReduceSumD(double v) {
    __shared__ double sh[32];
    int lane = threadIdx.x & 31, wid = threadIdx.x >> 5;
    #pragma unroll
    for (int o = 16; o; o >>= 1) v += __shfl_down_sync(0xffffffffu, v, o);
    if (lane == 0) sh[wid] = v;
    __syncthreads();
    int nw = (blockDim.x + 31) >> 5;
    v = (threadIdx.x < nw) ? sh[threadIdx.x] : 0.0;
    if (wid == 0) {
        #pragma unroll
        for (int o = 16; o; o >>= 1) v += __shfl_down_sync(0xffffffffu, v, o);
    }
    __syncthreads();
    return v;
}

// ---------------- kernel 1: per-primitive prep ----------------
// grid = BB*MM blocks, 256 threads. Block = b*MM + m.
__global__ void k_prep(const float* __restrict__ rot,
                       const float* __restrict__ size,
                       const float* __restrict__ shape,
                       const float* __restrict__ deform,
                       const float* __restrict__ emb)
{
    int blk = blockIdx.x;
    int b = blk / MM, m = blk % MM;
    __shared__ float sh[7];  // e1,e2,sx,sy,sz,dfx,dfy

    if (threadIdx.x == 0) {
        if (blk == 0) g_p2p = 0.0;
        // idx_e[b][m] = argmax_i emb[b][i][m] (first max on ties)
        int j = 0;
        float best = emb[(b * MM + 0) * MM + m];
        for (int i = 1; i < MM; i++) {
            float v = emb[(b * MM + i) * MM + m];
            if (v > best) { best = v; j = i; }
        }
        // rotation matrix of primitive m (NOT gathered)
        const float* q = rot + (b * MM + m) * 4;
        float w = q[0], x = q[1], y = q[2], z = q[3];
        float inv = rsqrtf(w * w + x * x + y * y + z * z);
        w *= inv; x *= inv; y *= inv; z *= inv;
        float* R = g_R + blk * 9;
        R[0] = 1.f - 2.f * (y * y + z * z); R[1] = 2.f * (x * y - w * z); R[2] = 2.f * (x * z + w * y);
        R[3] = 2.f * (x * y + w * z); R[4] = 1.f - 2.f * (x * x + z * z); R[5] = 2.f * (y * z - w * x);
        R[6] = 2.f * (x * z - w * y); R[7] = 2.f * (y * z + w * x); R[8] = 1.f - 2.f * (x * x + y * y);
        // gathered parameters (of primitive j)
        const float* sz3 = size   + (b * MM + j) * 3;
        const float* sh2 = shape  + (b * MM + j) * 2;
        const float* df2 = deform + (b * MM + j) * 2;
        sh[0] = sh2[0]; sh[1] = sh2[1];
        sh[2] = sz3[0]; sh[3] = sz3[1]; sh[4] = sz3[2];
        sh[5] = df2[0]; sh[6] = df2[1];
        // raw area from gathered size
        float a0 = sz3[0], a1 = sz3[1], a2 = sz3[2];
        float ar = powf(a0 * a1, 1.6f) / 3.f + powf(a0 * a2, 1.6f) / 3.f + powf(a1 * a2, 1.6f) / 3.f;
        g_area[blk] = 4.f * (float)M_PI * powf(ar, 0.625f);
    }
    __syncthreads();

    int s = threadIdx.x;
    if (s < SS) {
        float e1 = sh[0], e2 = sh[1], sx = sh[2], sy = sh[3], szv = sh[4];
        float dfx = sh[5], dfy = sh[6];
        double stepE = (M_PI - 0.1) / (double)(SS - 1);
        double stepO = (2.0 * M_PI - 0.1) / (double)(SS - 1);
        float eta = (float)(-M_PI / 2.0 + 0.05 + s * stepE);
        float omg = (float)(-M_PI + 0.05 + s * stepO);
        float ce = cosf(eta), se = sinf(eta), co = cosf(omg), so = sinf(omg);
        float fce = fexp_f(ce, e1);
        float x = sx * fce * fexp_f(co, e2);
        float y = sy * fce * fexp_f(so, e2);
        float z = szv * fexp_f(se, e1);
        float fx = dfx / szv * z + 1.f;
        float fy = dfy / szv * z + 1.f;
        g_pts[blk * SS + s] = make_float4(x * fx, y * fy, z, 0.f);
    }
}

// ---------------- kernel 2: pcl_to_prim ----------------
// grid = BB*(NN/128) blocks, 128 threads. Dynamic smem = MM*SS*sizeof(float4).
extern __shared__ float4 s_pts4[];
__global__ void k_p2p(const float* __restrict__ pcl,
                      const float* __restrict__ trans,
                      const float* __restrict__ prob)
{
    __shared__ float s_R[MM * 9];
    __shared__ float s_t[MM * 3];
    __shared__ float s_p[MM];
    const int perB = NN / 128;
    int b = blockIdx.x / perB;
    int chunk = blockIdx.x % perB;

    for (int i = threadIdx.x; i < MM * SS; i += blockDim.x)
        s_pts4[i] = g_pts[b * MM * SS + i];
    for (int i = threadIdx.x; i < MM * 9; i += blockDim.x)
        s_R[i] = g_R[b * MM * 9 + i];
    for (int i = threadIdx.x; i < MM * 3; i += blockDim.x)
        s_t[i] = trans[b * MM * 3 + i];
    if (threadIdx.x < MM) s_p[threadIdx.x] = prob[b * MM + threadIdx.x];
    __syncthreads();

    int n = chunk * 128 + threadIdx.x;
    const float* P = pcl + (b * NN + n) * 3;
    float px = P[0], py = P[1], pz = P[2];

    float dv[MM];
    for (int m = 0; m < MM; m++) {
        float ax = px - s_t[m * 3 + 0], ay = py - s_t[m * 3 + 1], az = pz - s_t[m * 3 + 2];
        const float* R = s_R + m * 9;
        float tx = R[0] * ax + R[1] * ay + R[2] * az;
        float ty = R[3] * ax + R[4] * ay + R[5] * az;
        float tz = R[6] * ax + R[7] * ay + R[8] * az;
        const float4* Q = s_pts4 + m * SS;
        float m0 = 3.4e38f, m1 = m0, m2 = m0, m3 = m0;
        #pragma unroll 5
        for (int s0 = 0; s0 < SS; s0 += 4) {
            float4 q0 = Q[s0 + 0], q1 = Q[s0 + 1], q2 = Q[s0 + 2], q3 = Q[s0 + 3];
            float dx, dy, dz, d;
            dx = q0.x - tx; dy = q0.y - ty; dz = q0.z - tz;
            d = fmaf(dx, dx, fmaf(dy, dy, dz * dz)); m0 = fminf(m0, d);
            dx = q1.x - tx; dy = q1.y - ty; dz = q1.z - tz;
            d = fmaf(dx, dx, fmaf(dy, dy, dz * dz)); m1 = fminf(m1, d);
            dx = q2.x - tx; dy = q2.y - ty; dz = q2.z - tz;
            d = fmaf(dx, dx, fmaf(dy, dy, dz * dz)); m2 = fminf(m2, d);
            dx = q3.x - tx; dy = q3.y - ty; dz = q3.z - tz;
            d = fmaf(dx, dx, fmaf(dy, dy, dz * dz)); m3 = fminf(m3, d);
        }
        dv[m] = fminf(fminf(m0, m1), fminf(m2, m3));
    }

    // stable insertion sort of (dv, index) ascending
    float sd[MM]; int idx[MM];
    for (int k = 0; k < MM; k++) {
        float v = dv[k];
        int p = k;
        while (p > 0 && sd[p - 1] > v) { sd[p] = sd[p - 1]; idx[p] = idx[p - 1]; p--; }
        sd[p] = v; idx[p] = k;
    }
    float cum = 1.f, acc = 0.f;
    #pragma unroll
    for (int k = 0; k < MM; k++) {
        float p = s_p[idx[k]];
        acc += sd[k] * p * cum;
        cum *= (1.f - p);
    }

    double total = blockReduceSumD((double)acc);
    if (threadIdx.x == 0) atomicAdd(&g_p2p, total);
}

// ---------------- kernel 3: prim_to_pcl (min over N) ----------------
// grid = BB*MM blocks, 256 threads.
__global__ void k_prim(const float* __restrict__ pcl,
                       const float* __restrict__ trans)
{
    int blk = blockIdx.x;
    int b = blk / MM;
    __shared__ float s_x[256], s_y[256], s_z[256];
    __shared__ float s_Rt[12];
    if (threadIdx.x < 9)  s_Rt[threadIdx.x] = g_R[blk * 9 + threadIdx.x];
    if (threadIdx.x < 3)  s_Rt[9 + threadIdx.x] = trans[blk * 3 + threadIdx.x];
    __syncthreads();
    float R0 = s_Rt[0], R1 = s_Rt[1], R2 = s_Rt[2];
    float R3 = s_Rt[3], R4 = s_Rt[4], R5 = s_Rt[5];
    float R6 = s_Rt[6], R7 = s_Rt[7], R8 = s_Rt[8];
    float t0 = s_Rt[9], t1 = s_Rt[10], t2 = s_Rt[11];

    bool act = threadIdx.x < SS;
    float qx = 0.f, qy = 0.f, qz = 0.f;
    if (act) {
        float4 q = g_pts[blk * SS + threadIdx.x];
        qx = q.x; qy = q.y; qz = q.z;
    }
    float m0 = 3.4e38f, m1 = m0, m2 = m0, m3 = m0;

    for (int base = 0; base < NN; base += 256) {
        int n = base + threadIdx.x;
        const float* P = pcl + (b * NN + n) * 3;
        float ax = P[0] - t0, ay = P[1] - t1, az = P[2] - t2;
        s_x[threadIdx.x] = R0 * ax + R1 * ay + R2 * az;
        s_y[threadIdx.x] = R3 * ax + R4 * ay + R5 * az;
        s_z[threadIdx.x] = R6 * ax + R7 * ay + R8 * az;
        __syncthreads();
        if (act) {
            #pragma unroll 4
            for (int k = 0; k < 256; k += 4) {
                float dx, dy, dz, d;
                dx = s_x[k]   - qx; dy = s_y[k]   - qy; dz = s_z[k]   - qz;
                d = fmaf(dx, dx, fmaf(dy, dy, dz * dz)); m0 = fminf(m0, d);
                dx = s_x[k+1] - qx; dy = s_y[k+1] - qy; dz = s_z[k+1] - qz;
                d = fmaf(dx, dx, fmaf(dy, dy, dz * dz)); m1 = fminf(m1, d);
                dx = s_x[k+2] - qx; dy = s_y[k+2] - qy; dz = s_z[k+2] - qz;
                d = fmaf(dx, dx, fmaf(dy, dy, dz * dz)); m2 = fminf(m2, d);
                dx = s_x[k+3] - qx; dy = s_y[k+3] - qy; dz = s_z[k+3] - qz;
                d = fmaf(dx, dx, fmaf(dy, dy, dz * dz)); m3 = fminf(m3, d);
            }
        }
        __syncthreads();
    }
    float dmin = fminf(fminf(m0, m1), fminf(m2, m3));
    if (dmin >= 1e30f) dmin = 0.f;     // matches jnp.where(d2>=1e30, 0, d2)
    double v = act ? (double)dmin : 0.0;
    double sum = blockReduceSumD(v);
    if (threadIdx.x == 0) g_d2sum[blk] = (float)sum;
}

// ---------------- kernel 4: embeddings regularizer ----------------
__global__ void k_emb(const float* __restrict__ e)
{
    int t = threadIdx.x;
    double c1 = 0.0, c2 = 0.0, c3 = 0.0;
    if (t < BB * MM) {
        int b = t / MM, k = t % MM;
        float s1 = 0.f, s2 = 0.f;
        for (int i = 0; i < MM; i++) {
            s1 += e[(b * MM + i) * MM + k];  // sum over axis 1
            s2 += e[(b * MM + k) * MM + i];  // sum over axis 2
        }
        float d1 = s1 - 1.f, d2 = s2 - 1.f;
        c1 = (double)(d1 * d1);
        c2 = (double)(d2 * d2);
    }
    for (int i = t; i < BB * MM * MM; i += blockDim.x) {
        float v = e[i];
        c3 += (double)(v * (1.f - v));
    }
    double r1 = blockReduceSumD(c1);
    double r2 = blockReduceSumD(c2);
    double r3 = blockReduceSumD(c3);
    if (t == 0)
        g_emb = r1 / (double)(BB * MM) + 10.0 * r2 / (double)(BB * MM)
              + r3 / (double)(BB * MM * MM);
}

// ---------------- kernel 5: finalize ----------------
__global__ void k_final(float* __restrict__ out)
{
    if (threadIdx.x == 0) {
        double p2p = g_p2p / (double)(BB * NN);
        double prim = 0.0;
        for (int b = 0; b < BB; b++) {
            float sa = 0.f;
            for (int m = 0; m < MM; m++) sa += g_area[b * MM + m];
            for (int m = 0; m < MM; m++) {
                double mean_d2 = (double)g_d2sum[b * MM + m] / (double)SS;
                double an = (double)MM * (double)g_area[b * MM + m] / (double)sa;
                prim += mean_d2 * an;
            }
        }
        prim /= (double)(BB * MM);
        double embv = g_emb;
        out[0] = (float)(p2p + prim + embv);
        out[1] = (float)p2p;
        out[2] = (float)prim;
        out[3] = 0.f;
        out[4] = (float)embv;
    }
}

// ---------------- launch ----------------
extern "C" void kernel_launch(void* const* d_in, const int* in_sizes, int n_in,
                              void* d_out, int out_size)
{
    const float* pcl    = (const float*)d_in[0];
    const float* trans  = (const float*)d_in[1];
    const float* rot    = (const float*)d_in[2];
    const float* size   = (const float*)d_in[3];
    const float* shape  = (const float*)d_in[4];
    const float* deform = (const float*)d_in[5];
    const float* prob   = (const float*)d_in[6];
    const float* emb    = (const float*)d_in[7];

    static bool attr_set = false;
    if (!attr_set) {
        cudaFuncSetAttribute(k_p2p, cudaFuncAttributeMaxDynamicSharedMemorySize,
                             MM * SS * (int)sizeof(float4) + 4096);
        attr_set = true;
    }

    k_prep<<<BB * MM, 256>>>(rot, size, shape, deform, emb);
    k_p2p<<<BB * (NN / 128), 128, MM * SS * (int)sizeof(float4)>>>(pcl, trans, prob);
    k_prim<<<BB * MM, 256>>>(pcl, trans);
    k_emb<<<1, 256>>>(emb);
    k_final<<<1, 32>>>((float*)d_out);
}

// round 3
// speedup vs baseline: 1.7513x; 1.7513x over previous
#include <cuda_runtime.h>
#include <math.h>

#define BB 4
#define NN 2048
#define MM 16
#define SS 200
#define CHUNKS 8            // N split into 8 chunks of 256

// ---------------- device scratch ----------------
__device__ float    g_R[BB * MM * 9];
__device__ float4   g_pts[BB * MM * SS];   // xyz deformed sample point, w = |q|^2
__device__ float    g_area[BB * MM];
__device__ float    g_dv[BB * MM * NN];    // [(b*MM+m)*NN + n]  min-over-S dist
__device__ unsigned g_dmin[BB * MM * SS];  // float bits of min-over-N dist (init +inf)
__device__ double   g_p2p;
__device__ double   g_emb;

__device__ __forceinline__ float fexp_f(float x, float p) {
    float s = (x > 0.f) ? 1.f : ((x < 0.f) ? -1.f : 0.f);
    return s * powf(fabsf(x) + 1e-6f, p);
}

__device__ __forceinline__ double blockReduceSumD(double v) {
    __shared__ double sh[32];
    int lane = threadIdx.x & 31, wid = threadIdx.x >> 5;
    #pragma unroll
    for (int o = 16; o; o >>= 1) v += __shfl_down_sync(0xffffffffu, v, o);
    if (lane == 0) sh[wid] = v;
    __syncthreads();
    int nw = (blockDim.x + 31) >> 5;
    v = (threadIdx.x < nw) ? sh[threadIdx.x] : 0.0;
    if (wid == 0) {
        #pragma unroll
        for (int o = 16; o; o >>= 1) v += __shfl_down_sync(0xffffffffu, v, o);
    }
    __syncthreads();
    return v;
}

// ---------------- kernel 1: prep (64 prim blocks + 1 emb block) ----------------
__global__ void k_prep(const float* __restrict__ rot,
                       const float* __restrict__ size,
                       const float* __restrict__ shape,
                       const float* __restrict__ deform,
                       const float* __restrict__ emb)
{
    int blk = blockIdx.x;

    if (blk == BB * MM) {
        // ---- embeddings regularizer ----
        int t = threadIdx.x;
        double c1 = 0.0, c2 = 0.0, c3 = 0.0;
        if (t < BB * MM) {
            int b = t / MM, k = t % MM;
            float s1 = 0.f, s2 = 0.f;
            for (int i = 0; i < MM; i++) {
                s1 += emb[(b * MM + i) * MM + k];
                s2 += emb[(b * MM + k) * MM + i];
            }
            float d1 = s1 - 1.f, d2 = s2 - 1.f;
            c1 = (double)(d1 * d1);
            c2 = (double)(d2 * d2);
        }
        for (int i = t; i < BB * MM * MM; i += blockDim.x) {
            float v = emb[i];
            c3 += (double)(v * (1.f - v));
        }
        double r1 = blockReduceSumD(c1);
        double r2 = blockReduceSumD(c2);
        double r3 = blockReduceSumD(c3);
        if (t == 0) {
            g_emb = r1 / (double)(BB * MM) + 10.0 * r2 / (double)(BB * MM)
                  + r3 / (double)(BB * MM * MM);
            g_p2p = 0.0;
        }
        return;
    }

    int b = blk / MM, m = blk % MM;
    __shared__ float sh[7];  // e1,e2,sx,sy,sz,dfx,dfy

    if (threadIdx.x == 0) {
        // idx_e[b][m] = argmax_i emb[b][i][m]
        int j = 0;
        float best = emb[(b * MM + 0) * MM + m];
        for (int i = 1; i < MM; i++) {
            float v = emb[(b * MM + i) * MM + m];
            if (v > best) { best = v; j = i; }
        }
        const float* q = rot + (b * MM + m) * 4;
        float w = q[0], x = q[1], y = q[2], z = q[3];
        float inv = rsqrtf(w * w + x * x + y * y + z * z);
        w *= inv; x *= inv; y *= inv; z *= inv;
        float* R = g_R + blk * 9;
        R[0] = 1.f - 2.f * (y * y + z * z); R[1] = 2.f * (x * y - w * z); R[2] = 2.f * (x * z + w * y);
        R[3] = 2.f * (x * y + w * z); R[4] = 1.f - 2.f * (x * x + z * z); R[5] = 2.f * (y * z - w * x);
        R[6] = 2.f * (x * z - w * y); R[7] = 2.f * (y * z + w * x); R[8] = 1.f - 2.f * (x * x + y * y);
        const float* sz3 = size   + (b * MM + j) * 3;
        const float* sh2 = shape  + (b * MM + j) * 2;
        const float* df2 = deform + (b * MM + j) * 2;
        sh[0] = sh2[0]; sh[1] = sh2[1];
        sh[2] = sz3[0]; sh[3] = sz3[1]; sh[4] = sz3[2];
        sh[5] = df2[0]; sh[6] = df2[1];
        float a0 = sz3[0], a1 = sz3[1], a2 = sz3[2];
        float ar = powf(a0 * a1, 1.6f) / 3.f + powf(a0 * a2, 1.6f) / 3.f + powf(a1 * a2, 1.6f) / 3.f;
        g_area[blk] = 4.f * (float)M_PI * powf(ar, 0.625f);
    }
    __syncthreads();

    int s = threadIdx.x;
    if (s < SS) {
        float e1 = sh[0], e2 = sh[1], sx = sh[2], sy = sh[3], szv = sh[4];
        float dfx = sh[5], dfy = sh[6];
        double stepE = (M_PI - 0.1) / (double)(SS - 1);
        double stepO = (2.0 * M_PI - 0.1) / (double)(SS - 1);
        float eta = (float)(-M_PI / 2.0 + 0.05 + s * stepE);
        float omg = (float)(-M_PI + 0.05 + s * stepO);
        float ce = cosf(eta), se = sinf(eta), co = cosf(omg), so = sinf(omg);
        float fce = fexp_f(ce, e1);
        float x = sx * fce * fexp_f(co, e2);
        float y = sy * fce * fexp_f(so, e2);
        float z = szv * fexp_f(se, e1);
        float fx = dfx / szv * z + 1.f;
        float fy = dfy / szv * z + 1.f;
        float X = x * fx, Y = y * fy, Z = z;
        g_pts[blk * SS + s] = make_float4(X, Y, Z, X * X + Y * Y + Z * Z);
        g_dmin[blk * SS + s] = 0x7F800000u;  // +inf bits (re-init every launch)
    }
}

// ---------------- kernel 2: fused distance field ----------------
// blocks [0, 512):   p2p phase 1 — per (b,m,chunk), min over S for 256 points
// blocks [512, 1024): prim partial — per (b,m,chunk), min over 256 points for S samples
__global__ void __launch_bounds__(256) k_main(const float* __restrict__ pcl,
                                              const float* __restrict__ trans)
{
    __shared__ float4 s_q[256];
    __shared__ float  s_R[9], s_t[3];
    int bid = blockIdx.x;
    int t = threadIdx.x;

    if (bid < BB * MM * CHUNKS) {
        // ---------- pcl -> prim: min over S ----------
        int b     = bid / (MM * CHUNKS);
        int m     = (bid / CHUNKS) % MM;
        int chunk = bid % CHUNKS;
        int blkm  = b * MM + m;

        if (t < SS) s_q[t] = g_pts[blkm * SS + t];
        if (t < 9)  s_R[t] = g_R[blkm * 9 + t];
        if (t < 3)  s_t[t] = trans[blkm * 3 + t];
        __syncthreads();

        int n = chunk * 256 + t;
        const float* P = pcl + (b * NN + n) * 3;
        float ax = P[0] - s_t[0], ay = P[1] - s_t[1], az = P[2] - s_t[2];
        float tx = s_R[0] * ax + s_R[1] * ay + s_R[2] * az;
        float ty = s_R[3] * ax + s_R[4] * ay + s_R[5] * az;
        float tz = s_R[6] * ax + s_R[7] * ay + s_R[8] * az;
        float tt  = fmaf(tx, tx, fmaf(ty, ty, tz * tz));
        float tx2 = -2.f * tx, ty2 = -2.f * ty, tz2 = -2.f * tz;

        float m0 = 3.4e38f, m1 = m0, m2 = m0, m3 = m0;
        #pragma unroll 5
        for (int s0 = 0; s0 < SS; s0 += 4) {
            float4 q0 = s_q[s0 + 0], q1 = s_q[s0 + 1], q2 = s_q[s0 + 2], q3 = s_q[s0 + 3];
            float v;
            v = fmaf(q0.x, tx2, fmaf(q0.y, ty2, fmaf(q0.z, tz2, q0.w))); m0 = fminf(m0, v);
            v = fmaf(q1.x, tx2, fmaf(q1.y, ty2, fmaf(q1.z, tz2, q1.w))); m1 = fminf(m1, v);
            v = fmaf(q2.x, tx2, fmaf(q2.y, ty2, fmaf(q2.z, tz2, q2.w))); m2 = fminf(m2, v);
            v = fmaf(q3.x, tx2, fmaf(q3.y, ty2, fmaf(q3.z, tz2, q3.w))); m3 = fminf(m3, v);
        }
        float d = fminf(fminf(m0, m1), fminf(m2, m3)) + tt;
        d = fmaxf(d, 0.f);
        g_dv[blkm * NN + n] = d;
    } else {
        // ---------- prim -> pcl: min over N (partial, atomicMin combine) ----------
        int pid   = bid - BB * MM * CHUNKS;
        int blkm  = pid / CHUNKS;
        int chunk = pid % CHUNKS;
        int b     = blkm / MM;

        if (t < 9) s_R[t] = g_R[blkm * 9 + t];
        if (t < 3) s_t[t] = trans[blkm * 3 + t];
        __syncthreads();

        int n = chunk * 256 + t;
        const float* P = pcl + (b * NN + n) * 3;
        float ax = P[0] - s_t[0], ay = P[1] - s_t[1], az = P[2] - s_t[2];
        float ux = s_R[0] * ax + s_R[1] * ay + s_R[2] * az;
        float uy = s_R[3] * ax + s_R[4] * ay + s_R[5] * az;
        float uz = s_R[6] * ax + s_R[7] * ay + s_R[8] * az;
        s_q[t] = make_float4(ux, uy, uz, fmaf(ux, ux, fmaf(uy, uy, uz * uz)));
        __syncthreads();

        if (t < SS) {
            float4 q = g_pts[blkm * SS + t];
            float qx2 = -2.f * q.x, qy2 = -2.f * q.y, qz2 = -2.f * q.z;
            float m0 = 3.4e38f, m1 = m0, m2 = m0, m3 = m0;
            #pragma unroll 4
            for (int k = 0; k < 256; k += 4) {
                float4 u0 = s_q[k + 0], u1 = s_q[k + 1], u2 = s_q[k + 2], u3 = s_q[k + 3];
                float v;
                v = fmaf(u0.x, qx2, fmaf(u0.y, qy2, fmaf(u0.z, qz2, u0.w))); m0 = fminf(m0, v);
                v = fmaf(u1.x, qx2, fmaf(u1.y, qy2, fmaf(u1.z, qz2, u1.w))); m1 = fminf(m1, v);
                v = fmaf(u2.x, qx2, fmaf(u2.y, qy2, fmaf(u2.z, qz2, u2.w))); m2 = fminf(m2, v);
                v = fmaf(u3.x, qx2, fmaf(u3.y, qy2, fmaf(u3.z, qz2, u3.w))); m3 = fminf(m3, v);
            }
            float d = fminf(fminf(m0, m1), fminf(m2, m3)) + q.w;
            d = fmaxf(d, 0.f);
            atomicMin(&g_dmin[blkm * SS + t], __float_as_uint(d));
        }
    }
}

// ---------------- kernel 3: p2p weighting (replaces sort+cumprod) ----------------
__global__ void __launch_bounds__(256) k_p2p2(const float* __restrict__ prob)
{
    __shared__ float s_p[MM];
    int b = blockIdx.x / CHUNKS, chunk = blockIdx.x % CHUNKS;
    int t = threadIdx.x;
    if (t < MM) s_p[t] = prob[b * MM + t];
    __syncthreads();

    int n = chunk * 256 + t;
    float dv[MM], pv[MM];
    #pragma unroll
    for (int m = 0; m < MM; m++) {
        dv[m] = g_dv[(b * MM + m) * NN + n];
        pv[m] = s_p[m];
    }
    float acc = 0.f;
    #pragma unroll
    for (int m = 0; m < MM; m++) {
        float w = pv[m];
        #pragma unroll
        for (int j = 0; j < MM; j++) {
            if (j == m) continue;
            // "j comes before m" in the stable ascending sort
            bool before = (dv[j] < dv[m]) || (dv[j] == dv[m] && j < m);
            w *= before ? (1.f - pv[j]) : 1.f;
        }
        acc = fmaf(dv[m], w, acc);
    }

    double tot = blockReduceSumD((double)acc);
    if (t == 0) atomicAdd(&g_p2p, tot);
}

// ---------------- kernel 4: finalize ----------------
__global__ void k_final(float* __restrict__ out)
{
    __shared__ float s_d2[BB * MM];
    int t = threadIdx.x;
    if (t < BB * MM) {
        float s = 0.f;
        #pragma unroll 8
        for (int i = 0; i < SS; i++) s += __uint_as_float(g_dmin[t * SS + i]);
        s_d2[t] = s;
    }
    __syncthreads();
    if (t == 0) {
        double p2p = g_p2p / (double)(BB * NN);
        double prim = 0.0;
        for (int b = 0; b < BB; b++) {
            float sa = 0.f;
            for (int m = 0; m < MM; m++) sa += g_area[b * MM + m];
            for (int m = 0; m < MM; m++) {
                double mean_d2 = (double)s_d2[b * MM + m] / (double)SS;
                double an = (double)MM * (double)g_area[b * MM + m] / (double)sa;
                prim += mean_d2 * an;
            }
        }
        prim /= (double)(BB * MM);
        double embv = g_emb;
        out[0] = (float)(p2p + prim + embv);
        out[1] = (float)p2p;
        out[2] = (float)prim;
        out[3] = 0.f;
        out[4] = (float)embv;
    }
}

// ---------------- launch ----------------
extern "C" void kernel_launch(void* const* d_in, const int* in_sizes, int n_in,
                              void* d_out, int out_size)
{
    const float* pcl    = (const float*)d_in[0];
    const float* trans  = (const float*)d_in[1];
    const float* rot    = (const float*)d_in[2];
    const float* size   = (const float*)d_in[3];
    const float* shape  = (const float*)d_in[4];
    const float* deform = (const float*)d_in[5];
    const float* prob   = (const float*)d_in[6];
    const float* emb    = (const float*)d_in[7];

    k_prep <<<BB * MM + 1, 256>>>(rot, size, shape, deform, emb);
    k_main <<<BB * MM * CHUNKS * 2, 256>>>(pcl, trans);
    k_p2p2 <<<BB * CHUNKS, 256>>>(prob);
    k_final<<<1, 256>>>((float*)d_out);
}

// round 4
// speedup vs baseline: 2.6244x; 1.4985x over previous
#include <cuda_runtime.h>
#include <math.h>

#define BB 4
#define NN 2048
#define MM 16
#define SS 200
#define CHUNKS 8            // N split into 8 chunks of 256

// ---------------- device scratch ----------------
__device__ float    g_R[BB * MM * 9];
__device__ float4   g_pts[BB * MM * SS];   // xyz deformed sample point, w = |q|^2
__device__ float    g_area[BB * MM];
__device__ float    g_dv[BB * MM * NN];    // [(b*MM+m)*NN + n]  min-over-S dist
__device__ unsigned g_dmin[BB * MM * SS];  // float bits of min-over-N dist (init +inf)
__device__ double   g_p2p;
__device__ double   g_prim;
__device__ double   g_emb;

__device__ __forceinline__ float fexp_f(float x, float p) {
    float s = (x > 0.f) ? 1.f : ((x < 0.f) ? -1.f : 0.f);
    return s * powf(fabsf(x) + 1e-6f, p);
}

__device__ __forceinline__ double blockReduceSumD(double v) {
    __shared__ double sh[32];
    int lane = threadIdx.x & 31, wid = threadIdx.x >> 5;
    #pragma unroll
    for (int o = 16; o; o >>= 1) v += __shfl_down_sync(0xffffffffu, v, o);
    if (lane == 0) sh[wid] = v;
    __syncthreads();
    int nw = (blockDim.x + 31) >> 5;
    v = (threadIdx.x < nw) ? sh[threadIdx.x] : 0.0;
    if (wid == 0) {
        #pragma unroll
        for (int o = 16; o; o >>= 1) v += __shfl_down_sync(0xffffffffu, v, o);
    }
    __syncthreads();
    return v;
}

// ---------------- kernel 1: prep (64 prim blocks + 1 emb block) ----------------
__global__ void k_prep(const float* __restrict__ rot,
                       const float* __restrict__ size,
                       const float* __restrict__ shape,
                       const float* __restrict__ deform,
                       const float* __restrict__ emb)
{
    int blk = blockIdx.x;

    if (blk == BB * MM) {
        // ---- embeddings regularizer ----
        int t = threadIdx.x;
        double c1 = 0.0, c2 = 0.0, c3 = 0.0;
        if (t < BB * MM) {
            int b = t / MM, k = t % MM;
            float s1 = 0.f, s2 = 0.f;
            for (int i = 0; i < MM; i++) {
                s1 += emb[(b * MM + i) * MM + k];
                s2 += emb[(b * MM + k) * MM + i];
            }
            float d1 = s1 - 1.f, d2 = s2 - 1.f;
            c1 = (double)(d1 * d1);
            c2 = (double)(d2 * d2);
        }
        for (int i = t; i < BB * MM * MM; i += blockDim.x) {
            float v = emb[i];
            c3 += (double)(v * (1.f - v));
        }
        double r1 = blockReduceSumD(c1);
        double r2 = blockReduceSumD(c2);
        double r3 = blockReduceSumD(c3);
        if (t == 0) {
            g_emb = r1 / (double)(BB * MM) + 10.0 * r2 / (double)(BB * MM)
                  + r3 / (double)(BB * MM * MM);
            g_p2p = 0.0;
            g_prim = 0.0;
        }
        return;
    }

    int b = blk / MM, m = blk % MM;
    __shared__ float sh[7];  // e1,e2,sx,sy,sz,dfx,dfy

    if (threadIdx.x == 0) {
        // idx_e[b][m] = argmax_i emb[b][i][m]
        int j = 0;
        float best = emb[(b * MM + 0) * MM + m];
        for (int i = 1; i < MM; i++) {
            float v = emb[(b * MM + i) * MM + m];
            if (v > best) { best = v; j = i; }
        }
        const float* q = rot + (b * MM + m) * 4;
        float w = q[0], x = q[1], y = q[2], z = q[3];
        float inv = rsqrtf(w * w + x * x + y * y + z * z);
        w *= inv; x *= inv; y *= inv; z *= inv;
        float* R = g_R + blk * 9;
        R[0] = 1.f - 2.f * (y * y + z * z); R[1] = 2.f * (x * y - w * z); R[2] = 2.f * (x * z + w * y);
        R[3] = 2.f * (x * y + w * z); R[4] = 1.f - 2.f * (x * x + z * z); R[5] = 2.f * (y * z - w * x);
        R[6] = 2.f * (x * z - w * y); R[7] = 2.f * (y * z + w * x); R[8] = 1.f - 2.f * (x * x + y * y);
        const float* sz3 = size   + (b * MM + j) * 3;
        const float* sh2 = shape  + (b * MM + j) * 2;
        const float* df2 = deform + (b * MM + j) * 2;
        sh[0] = sh2[0]; sh[1] = sh2[1];
        sh[2] = sz3[0]; sh[3] = sz3[1]; sh[4] = sz3[2];
        sh[5] = df2[0]; sh[6] = df2[1];
        float a0 = sz3[0], a1 = sz3[1], a2 = sz3[2];
        float ar = powf(a0 * a1, 1.6f) / 3.f + powf(a0 * a2, 1.6f) / 3.f + powf(a1 * a2, 1.6f) / 3.f;
        g_area[blk] = 4.f * (float)M_PI * powf(ar, 0.625f);
    }
    __syncthreads();

    int s = threadIdx.x;
    if (s < SS) {
        float e1 = sh[0], e2 = sh[1], sx = sh[2], sy = sh[3], szv = sh[4];
        float dfx = sh[5], dfy = sh[6];
        double stepE = (M_PI - 0.1) / (double)(SS - 1);
        double stepO = (2.0 * M_PI - 0.1) / (double)(SS - 1);
        float eta = (float)(-M_PI / 2.0 + 0.05 + s * stepE);
        float omg = (float)(-M_PI + 0.05 + s * stepO);
        float ce = cosf(eta), se = sinf(eta), co = cosf(omg), so = sinf(omg);
        float fce = fexp_f(ce, e1);
        float x = sx * fce * fexp_f(co, e2);
        float y = sy * fce * fexp_f(so, e2);
        float z = szv * fexp_f(se, e1);
        float fx = dfx / szv * z + 1.f;
        float fy = dfy / szv * z + 1.f;
        float X = x * fx, Y = y * fy, Z = z;
        g_pts[blk * SS + s] = make_float4(X, Y, Z, X * X + Y * Y + Z * Z);
        g_dmin[blk * SS + s] = 0x7F800000u;  // +inf bits (re-init every launch)
    }
}

// ---------------- kernel 2: fused distance field ----------------
// blocks [0, 512):   p2p phase 1 — per (b,m,chunk), min over S for 256 points
// blocks [512, 1024): prim partial — per (b,m,chunk), min over 256 points for S samples
__global__ void __launch_bounds__(256) k_main(const float* __restrict__ pcl,
                                              const float* __restrict__ trans)
{
    __shared__ float4 s_q[256];
    __shared__ float  s_R[9], s_t[3];
    int bid = blockIdx.x;
    int t = threadIdx.x;

    if (bid < BB * MM * CHUNKS) {
        // ---------- pcl -> prim: min over S ----------
        int b     = bid / (MM * CHUNKS);
        int m     = (bid / CHUNKS) % MM;
        int chunk = bid % CHUNKS;
        int blkm  = b * MM + m;

        if (t < SS) s_q[t] = g_pts[blkm * SS + t];
        if (t < 9)  s_R[t] = g_R[blkm * 9 + t];
        if (t < 3)  s_t[t] = trans[blkm * 3 + t];
        __syncthreads();

        int n = chunk * 256 + t;
        const float* P = pcl + (b * NN + n) * 3;
        float ax = P[0] - s_t[0], ay = P[1] - s_t[1], az = P[2] - s_t[2];
        float tx = s_R[0] * ax + s_R[1] * ay + s_R[2] * az;
        float ty = s_R[3] * ax + s_R[4] * ay + s_R[5] * az;
        float tz = s_R[6] * ax + s_R[7] * ay + s_R[8] * az;
        float tt  = fmaf(tx, tx, fmaf(ty, ty, tz * tz));
        float tx2 = -2.f * tx, ty2 = -2.f * ty, tz2 = -2.f * tz;

        float m0 = 3.4e38f, m1 = m0, m2 = m0, m3 = m0;
        #pragma unroll 5
        for (int s0 = 0; s0 < SS; s0 += 4) {
            float4 q0 = s_q[s0 + 0], q1 = s_q[s0 + 1], q2 = s_q[s0 + 2], q3 = s_q[s0 + 3];
            float v;
            v = fmaf(q0.x, tx2, fmaf(q0.y, ty2, fmaf(q0.z, tz2, q0.w))); m0 = fminf(m0, v);
            v = fmaf(q1.x, tx2, fmaf(q1.y, ty2, fmaf(q1.z, tz2, q1.w))); m1 = fminf(m1, v);
            v = fmaf(q2.x, tx2, fmaf(q2.y, ty2, fmaf(q2.z, tz2, q2.w))); m2 = fminf(m2, v);
            v = fmaf(q3.x, tx2, fmaf(q3.y, ty2, fmaf(q3.z, tz2, q3.w))); m3 = fminf(m3, v);
        }
        float d = fminf(fminf(m0, m1), fminf(m2, m3)) + tt;
        d = fmaxf(d, 0.f);
        g_dv[blkm * NN + n] = d;
    } else {
        // ---------- prim -> pcl: min over N (partial, atomicMin combine) ----------
        int pid   = bid - BB * MM * CHUNKS;
        int blkm  = pid / CHUNKS;
        int chunk = pid % CHUNKS;
        int b     = blkm / MM;

        if (t < 9) s_R[t] = g_R[blkm * 9 + t];
        if (t < 3) s_t[t] = trans[blkm * 3 + t];
        __syncthreads();

        int n = chunk * 256 + t;
        const float* P = pcl + (b * NN + n) * 3;
        float ax = P[0] - s_t[0], ay = P[1] - s_t[1], az = P[2] - s_t[2];
        float ux = s_R[0] * ax + s_R[1] * ay + s_R[2] * az;
        float uy = s_R[3] * ax + s_R[4] * ay + s_R[5] * az;
        float uz = s_R[6] * ax + s_R[7] * ay + s_R[8] * az;
        s_q[t] = make_float4(ux, uy, uz, fmaf(ux, ux, fmaf(uy, uy, uz * uz)));
        __syncthreads();

        if (t < SS) {
            float4 q = g_pts[blkm * SS + t];
            float qx2 = -2.f * q.x, qy2 = -2.f * q.y, qz2 = -2.f * q.z;
            float m0 = 3.4e38f, m1 = m0, m2 = m0, m3 = m0;
            #pragma unroll 4
            for (int k = 0; k < 256; k += 4) {
                float4 u0 = s_q[k + 0], u1 = s_q[k + 1], u2 = s_q[k + 2], u3 = s_q[k + 3];
                float v;
                v = fmaf(u0.x, qx2, fmaf(u0.y, qy2, fmaf(u0.z, qz2, u0.w))); m0 = fminf(m0, v);
                v = fmaf(u1.x, qx2, fmaf(u1.y, qy2, fmaf(u1.z, qz2, u1.w))); m1 = fminf(m1, v);
                v = fmaf(u2.x, qx2, fmaf(u2.y, qy2, fmaf(u2.z, qz2, u2.w))); m2 = fminf(m2, v);
                v = fmaf(u3.x, qx2, fmaf(u3.y, qy2, fmaf(u3.z, qz2, u3.w))); m3 = fminf(m3, v);
            }
            float d = fminf(fminf(m0, m1), fminf(m2, m3)) + q.w;
            d = fmaxf(d, 0.f);
            atomicMin(&g_dmin[blkm * SS + t], __float_as_uint(d));
        }
    }
}

// ---------------- kernel 3: tail — p2p weighting blocks + one prim-sum block ----------------
__global__ void __launch_bounds__(256) k_tail(const float* __restrict__ prob)
{
    int bid = blockIdx.x;
    int t = threadIdx.x;

    if (bid < BB * CHUNKS) {
        // ---- p2p weighting (replaces sort+cumprod) ----
        __shared__ float s_p[MM];
        int b = bid / CHUNKS, chunk = bid % CHUNKS;
        if (t < MM) s_p[t] = prob[b * MM + t];
        __syncthreads();

        int n = chunk * 256 + t;
        float dv[MM], pv[MM];
        #pragma unroll
        for (int m = 0; m < MM; m++) {
            dv[m] = g_dv[(b * MM + m) * NN + n];
            pv[m] = s_p[m];
        }
        float acc = 0.f;
        #pragma unroll
        for (int m = 0; m < MM; m++) {
            float w = pv[m];
            #pragma unroll
            for (int j = 0; j < MM; j++) {
                if (j == m) continue;
                bool before = (dv[j] < dv[m]) || (dv[j] == dv[m] && j < m);
                w *= before ? (1.f - pv[j]) : 1.f;
            }
            acc = fmaf(dv[m], w, acc);
        }
        double tot = blockReduceSumD((double)acc);
        if (t == 0) atomicAdd(&g_p2p, tot);
    } else {
        // ---- prim_to_pcl: flat weighted sum over g_dmin ----
        __shared__ float s_w[BB * MM];   // per-(b,m) weight
        __shared__ float s_a[BB * MM];
        if (t < BB * MM) s_a[t] = g_area[t];
        __syncthreads();
        if (t < BB * MM) {
            int b = t / MM;
            float sa = 0.f;
            #pragma unroll
            for (int m = 0; m < MM; m++) sa += s_a[b * MM + m];
            // w = (M * area / sa) / (SS * B * M)
            s_w[t] = s_a[t] / sa / (float)(SS * BB);
        }
        __syncthreads();

        double acc = 0.0;
        #pragma unroll 4
        for (int i = t; i < BB * MM * SS; i += 256) {
            float v = __uint_as_float(g_dmin[i]);
            v = (v >= 1e30f) ? 0.f : v;
            int blkm = i / SS;
            acc += (double)(v * s_w[blkm]);
        }
        double tot = blockReduceSumD(acc);
        if (t == 0) g_prim = tot;
    }
}

// ---------------- kernel 4: finalize (trivial) ----------------
__global__ void k_final(float* __restrict__ out)
{
    if (threadIdx.x == 0) {
        double p2p  = g_p2p / (double)(BB * NN);
        double prim = g_prim;
        double embv = g_emb;
        out[0] = (float)(p2p + prim + embv);
        out[1] = (float)p2p;
        out[2] = (float)prim;
        out[3] = 0.f;
        out[4] = (float)embv;
    }
}

// ---------------- launch ----------------
extern "C" void kernel_launch(void* const* d_in, const int* in_sizes, int n_in,
                              void* d_out, int out_size)
{
    const float* pcl    = (const float*)d_in[0];
    const float* trans  = (const float*)d_in[1];
    const float* rot    = (const float*)d_in[2];
    const float* size   = (const float*)d_in[3];
    const float* shape  = (const float*)d_in[4];
    const float* deform = (const float*)d_in[5];
    const float* prob   = (const float*)d_in[6];
    const float* emb    = (const float*)d_in[7];

    k_prep <<<BB * MM + 1, 256>>>(rot, size, shape, deform, emb);
    k_main <<<BB * MM * CHUNKS * 2, 256>>>(pcl, trans);
    k_tail <<<BB * CHUNKS + 1, 256>>>(prob);
    k_final<<<1, 32>>>((float*)d_out);
}

// round 5
// speedup vs baseline: 2.7449x; 1.0459x over previous
#include <cuda_runtime.h>
#include <math.h>

#define BB 4
#define NN 2048
#define MM 16
#define SS 200
#define CHUNKS 8            // N split into 8 chunks of 256

#define P2P_BLOCKS   (BB * MM * CHUNKS)        // 512
#define FUSED_BLOCKS (P2P_BLOCKS * 2)          // 1024
#define TAIL_P2P     (BB * CHUNKS)             // 32
#define TAIL_PRIM    8
#define TAIL_BLOCKS  (TAIL_P2P + TAIL_PRIM)    // 40

// ---------------- device scratch ----------------
__device__ float    g_dv[BB * MM * NN];                 // min-over-S dist per (blkm, n)
__device__ float    g_dpart[BB * MM * CHUNKS * SS];     // per-chunk partial min-over-n
__device__ double   g_part[TAIL_BLOCKS];                // per-tail-block partial sums
__device__ double   g_emb;
__device__ unsigned g_cnt;                              // last-block ticket (self-resetting)

__device__ __forceinline__ float fexp_f(float x, float p) {
    float s = (x > 0.f) ? 1.f : ((x < 0.f) ? -1.f : 0.f);
    return s * powf(fabsf(x) + 1e-6f, p);
}

__device__ __forceinline__ double blockReduceSumD(double v) {
    __shared__ double sh[32];
    int lane = threadIdx.x & 31, wid = threadIdx.x >> 5;
    #pragma unroll
    for (int o = 16; o; o >>= 1) v += __shfl_down_sync(0xffffffffu, v, o);
    if (lane == 0) sh[wid] = v;
    __syncthreads();
    int nw = (blockDim.x + 31) >> 5;
    v = (threadIdx.x < nw) ? sh[threadIdx.x] : 0.0;
    if (wid == 0) {
        #pragma unroll
        for (int o = 16; o; o >>= 1) v += __shfl_down_sync(0xffffffffu, v, o);
    }
    __syncthreads();
    return v;
}

// argmax_i emb[b][i][m]  (first max on ties)
__device__ __forceinline__ int argmax_col(const float* __restrict__ emb, int b, int m) {
    int j = 0;
    float best = emb[(b * MM + 0) * MM + m];
    #pragma unroll
    for (int i = 1; i < MM; i++) {
        float v = emb[(b * MM + i) * MM + m];
        if (v > best) { best = v; j = i; }
    }
    return j;
}

// ---------------- kernel 1: fused prep + distance field ----------------
// blocks [0, 512):    p2p — per (blkm, chunk), min over S for 256 points -> g_dv
// blocks [512, 1024): prim — per (blkm, chunk), partial min over 256 points -> g_dpart
__global__ void __launch_bounds__(256) k_fused(const float* __restrict__ pcl,
                                               const float* __restrict__ trans,
                                               const float* __restrict__ rot,
                                               const float* __restrict__ size,
                                               const float* __restrict__ shape,
                                               const float* __restrict__ deform,
                                               const float* __restrict__ emb)
{
    __shared__ float4 s_q[SS];       // sample points (xyz, |q|^2)
    __shared__ float4 s_u[256];      // transformed cloud points (prim side)
    __shared__ float  s_R[9], s_t[3], s_par[7];

    int bid = blockIdx.x, t = threadIdx.x;
    int side  = (bid >= P2P_BLOCKS);           // 0 = p2p, 1 = prim
    int pid   = side ? bid - P2P_BLOCKS : bid;
    int blkm  = pid / CHUNKS;
    int chunk = pid % CHUNKS;
    int b     = blkm / MM, m = blkm % MM;

    if (t == 0) {
        int j = argmax_col(emb, b, m);
        const float* q = rot + blkm * 4;
        float w = q[0], x = q[1], y = q[2], z = q[3];
        float inv = rsqrtf(w * w + x * x + y * y + z * z);
        w *= inv; x *= inv; y *= inv; z *= inv;
        s_R[0] = 1.f - 2.f * (y * y + z * z); s_R[1] = 2.f * (x * y - w * z); s_R[2] = 2.f * (x * z + w * y);
        s_R[3] = 2.f * (x * y + w * z); s_R[4] = 1.f - 2.f * (x * x + z * z); s_R[5] = 2.f * (y * z - w * x);
        s_R[6] = 2.f * (x * z - w * y); s_R[7] = 2.f * (y * z + w * x); s_R[8] = 1.f - 2.f * (x * x + y * y);
        s_t[0] = trans[blkm * 3 + 0]; s_t[1] = trans[blkm * 3 + 1]; s_t[2] = trans[blkm * 3 + 2];
        const float* sz3 = size   + (b * MM + j) * 3;
        const float* sh2 = shape  + (b * MM + j) * 2;
        const float* df2 = deform + (b * MM + j) * 2;
        s_par[0] = sh2[0]; s_par[1] = sh2[1];
        s_par[2] = sz3[0]; s_par[3] = sz3[1]; s_par[4] = sz3[2];
        s_par[5] = df2[0]; s_par[6] = df2[1];
    }
    __syncthreads();

    // sample points (all blocks), transformed cloud (prim side)
    if (t < SS) {
        float e1 = s_par[0], e2 = s_par[1];
        float sx = s_par[2], sy = s_par[3], szv = s_par[4];
        float dfx = s_par[5], dfy = s_par[6];
        double stepE = (M_PI - 0.1) / (double)(SS - 1);
        double stepO = (2.0 * M_PI - 0.1) / (double)(SS - 1);
        float eta = (float)(-M_PI / 2.0 + 0.05 + t * stepE);
        float omg = (float)(-M_PI + 0.05 + t * stepO);
        float ce = cosf(eta), se = sinf(eta), co = cosf(omg), so = sinf(omg);
        float fce = fexp_f(ce, e1);
        float x = sx * fce * fexp_f(co, e2);
        float y = sy * fce * fexp_f(so, e2);
        float z = szv * fexp_f(se, e1);
        float fx = dfx / szv * z + 1.f;
        float fy = dfy / szv * z + 1.f;
        float X = x * fx, Y = y * fy, Z = z;
        s_q[t] = make_float4(X, Y, Z, X * X + Y * Y + Z * Z);
    }
    if (side) {
        int n = chunk * 256 + t;
        const float* P = pcl + (b * NN + n) * 3;
        float ax = P[0] - s_t[0], ay = P[1] - s_t[1], az = P[2] - s_t[2];
        float ux = s_R[0] * ax + s_R[1] * ay + s_R[2] * az;
        float uy = s_R[3] * ax + s_R[4] * ay + s_R[5] * az;
        float uz = s_R[6] * ax + s_R[7] * ay + s_R[8] * az;
        s_u[t] = make_float4(ux, uy, uz, fmaf(ux, ux, fmaf(uy, uy, uz * uz)));
    }
    __syncthreads();

    if (!side) {
        // ---------- pcl -> prim: min over S ----------
        int n = chunk * 256 + t;
        const float* P = pcl + (b * NN + n) * 3;
        float ax = P[0] - s_t[0], ay = P[1] - s_t[1], az = P[2] - s_t[2];
        float tx = s_R[0] * ax + s_R[1] * ay + s_R[2] * az;
        float ty = s_R[3] * ax + s_R[4] * ay + s_R[5] * az;
        float tz = s_R[6] * ax + s_R[7] * ay + s_R[8] * az;
        float tt  = fmaf(tx, tx, fmaf(ty, ty, tz * tz));
        float tx2 = -2.f * tx, ty2 = -2.f * ty, tz2 = -2.f * tz;

        float m0 = 3.4e38f, m1 = m0, m2 = m0, m3 = m0;
        #pragma unroll 5
        for (int s0 = 0; s0 < SS; s0 += 4) {
            float4 q0 = s_q[s0 + 0], q1 = s_q[s0 + 1], q2 = s_q[s0 + 2], q3 = s_q[s0 + 3];
            float v;
            v = fmaf(q0.x, tx2, fmaf(q0.y, ty2, fmaf(q0.z, tz2, q0.w))); m0 = fminf(m0, v);
            v = fmaf(q1.x, tx2, fmaf(q1.y, ty2, fmaf(q1.z, tz2, q1.w))); m1 = fminf(m1, v);
            v = fmaf(q2.x, tx2, fmaf(q2.y, ty2, fmaf(q2.z, tz2, q2.w))); m2 = fminf(m2, v);
            v = fmaf(q3.x, tx2, fmaf(q3.y, ty2, fmaf(q3.z, tz2, q3.w))); m3 = fminf(m3, v);
        }
        float d = fminf(fminf(m0, m1), fminf(m2, m3)) + tt;
        d = fmaxf(d, 0.f);
        g_dv[blkm * NN + n] = d;
    } else {
        // ---------- prim -> pcl: partial min over this chunk's 256 points ----------
        if (t < SS) {
            float4 q = s_q[t];
            float qx2 = -2.f * q.x, qy2 = -2.f * q.y, qz2 = -2.f * q.z;
            float m0 = 3.4e38f, m1 = m0, m2 = m0, m3 = m0;
            #pragma unroll 4
            for (int k = 0; k < 256; k += 4) {
                float4 u0 = s_u[k + 0], u1 = s_u[k + 1], u2 = s_u[k + 2], u3 = s_u[k + 3];
                float v;
                v = fmaf(u0.x, qx2, fmaf(u0.y, qy2, fmaf(u0.z, qz2, u0.w))); m0 = fminf(m0, v);
                v = fmaf(u1.x, qx2, fmaf(u1.y, qy2, fmaf(u1.z, qz2, u1.w))); m1 = fminf(m1, v);
                v = fmaf(u2.x, qx2, fmaf(u2.y, qy2, fmaf(u2.z, qz2, u2.w))); m2 = fminf(m2, v);
                v = fmaf(u3.x, qx2, fmaf(u3.y, qy2, fmaf(u3.z, qz2, u3.w))); m3 = fminf(m3, v);
            }
            float d = fminf(fminf(m0, m1), fminf(m2, m3)) + q.w;
            d = fmaxf(d, 0.f);
            g_dpart[(blkm * CHUNKS + chunk) * SS + t] = d;
        }
    }
}

// ---------------- kernel 2: tail — p2p weighting, prim reduce, emb reg, final ----------------
__global__ void __launch_bounds__(256) k_tail(const float* __restrict__ prob,
                                              const float* __restrict__ size,
                                              const float* __restrict__ emb,
                                              float* __restrict__ out)
{
    __shared__ bool s_last;
    int bid = blockIdx.x, t = threadIdx.x;
    double part = 0.0;

    if (bid < TAIL_P2P) {
        // ---- p2p weighting (branch-free stable sort+cumprod equivalent) ----
        __shared__ float s_p[MM];
        int b = bid / CHUNKS, chunk = bid % CHUNKS;
        if (t < MM) s_p[t] = prob[b * MM + t];
        __syncthreads();

        int n = chunk * 256 + t;
        float dv[MM], pv[MM];
        #pragma unroll
        for (int mm = 0; mm < MM; mm++) {
            dv[mm] = g_dv[(b * MM + mm) * NN + n];
            pv[mm] = s_p[mm];
        }
        float acc = 0.f;
        #pragma unroll
        for (int mm = 0; mm < MM; mm++) {
            float w = pv[mm];
            #pragma unroll
            for (int j = 0; j < MM; j++) {
                if (j == mm) continue;
                bool before = (dv[j] < dv[mm]) || (dv[j] == dv[mm] && j < mm);
                w *= before ? (1.f - pv[j]) : 1.f;
            }
            acc = fmaf(dv[mm], w, acc);
        }
        part = blockReduceSumD((double)acc) / (double)(BB * NN);
    } else {
        // ---- prim partial reduction: 8 blkm per block ----
        int pid = bid - TAIL_P2P;               // 0..7
        int blkm0 = pid * 8;                     // first blkm of this block
        int b = blkm0 / MM;                      // all 8 share the same batch
        __shared__ float s_a[MM];
        __shared__ float s_w[8];

        if (t < MM) {
            int j = argmax_col(emb, b, t);
            const float* sz3 = size + (b * MM + j) * 3;
            float a0 = sz3[0], a1 = sz3[1], a2 = sz3[2];
            float ar = powf(a0 * a1, 1.6f) / 3.f + powf(a0 * a2, 1.6f) / 3.f + powf(a1 * a2, 1.6f) / 3.f;
            s_a[t] = 4.f * (float)M_PI * powf(ar, 0.625f);
        }
        __syncthreads();
        if (t < 8) {
            float sa = 0.f;
            #pragma unroll
            for (int mm = 0; mm < MM; mm++) sa += s_a[mm];
            int m_in_b = (blkm0 % MM) + t;
            s_w[t] = s_a[m_in_b] / sa / (float)(SS * BB);
        }
        __syncthreads();

        double acc = 0.0;
        for (int i = t; i < 8 * SS; i += 256) {
            int bl = i / SS, s = i % SS;
            const float* base = g_dpart + ((blkm0 + bl) * CHUNKS) * SS + s;
            float v = base[0];
            #pragma unroll
            for (int c = 1; c < CHUNKS; c++) v = fminf(v, base[c * SS]);
            v = (v >= 1e30f) ? 0.f : v;
            acc += (double)(v * s_w[bl]);
        }
        part = blockReduceSumD(acc);

        if (pid == 0) {
            // ---- embeddings regularizer (extra duty for this block) ----
            double c1 = 0.0, c2 = 0.0, c3 = 0.0;
            if (t < BB * MM) {
                int bb = t / MM, k = t % MM;
                float s1 = 0.f, s2 = 0.f;
                for (int i = 0; i < MM; i++) {
                    s1 += emb[(bb * MM + i) * MM + k];
                    s2 += emb[(bb * MM + k) * MM + i];
                }
                float d1 = s1 - 1.f, d2 = s2 - 1.f;
                c1 = (double)(d1 * d1);
                c2 = (double)(d2 * d2);
            }
            for (int i = t; i < BB * MM * MM; i += 256) {
                float v = emb[i];
                c3 += (double)(v * (1.f - v));
            }
            double r1 = blockReduceSumD(c1);
            double r2 = blockReduceSumD(c2);
            double r3 = blockReduceSumD(c3);
            if (t == 0)
                g_emb = r1 / (double)(BB * MM) + 10.0 * r2 / (double)(BB * MM)
                      + r3 / (double)(BB * MM * MM);
        }
    }

    if (t == 0) g_part[bid] = part;
    __threadfence();
    if (t == 0) {
        unsigned tk = atomicAdd(&g_cnt, 1u);
        s_last = (tk == (unsigned)(TAIL_BLOCKS - 1));
    }
    __syncthreads();

    if (s_last && t == 0) {
        double p2p = 0.0, prim = 0.0;
        #pragma unroll
        for (int i = 0; i < TAIL_P2P; i++)  p2p  += __ldcg(&g_part[i]);
        #pragma unroll
        for (int i = TAIL_P2P; i < TAIL_BLOCKS; i++) prim += __ldcg(&g_part[i]);
        double embv = __ldcg(&g_emb);
        out[0] = (float)(p2p + prim + embv);
        out[1] = (float)p2p;
        out[2] = (float)prim;
        out[3] = 0.f;
        out[4] = (float)embv;
        g_cnt = 0;   // reset for next graph replay
    }
}

// ---------------- launch ----------------
extern "C" void kernel_launch(void* const* d_in, const int* in_sizes, int n_in,
                              void* d_out, int out_size)
{
    const float* pcl    = (const float*)d_in[0];
    const float* trans  = (const float*)d_in[1];
    const float* rot    = (const float*)d_in[2];
    const float* size   = (const float*)d_in[3];
    const float* shape  = (const float*)d_in[4];
    const float* deform = (const float*)d_in[5];
    const float* prob   = (const float*)d_in[6];
    const float* emb    = (const float*)d_in[7];

    k_fused<<<FUSED_BLOCKS, 256>>>(pcl, trans, rot, size, shape, deform, emb);
    k_tail <<<TAIL_BLOCKS, 256>>>(prob, size, emb, (float*)d_out);
}

// round 6
// speedup vs baseline: 2.9922x; 1.0901x over previous
#include <cuda_runtime.h>
#include <math.h>

#define BB 4
#define NN 2048
#define MM 16
#define SS 200
#define CHUNKS 8            // N split into 8 chunks of 256

#define P2P_BLOCKS   (BB * MM * CHUNKS)        // 512
#define FUSED_BLOCKS (P2P_BLOCKS * 2)          // 1024 (+1 emb block)
#define TAIL_P2P     (BB * CHUNKS)             // 32
#define TAIL_PRIM    8
#define TAIL_BLOCKS  (TAIL_P2P + TAIL_PRIM)    // 40

typedef unsigned long long ull;

// ---------------- device scratch ----------------
__device__ float    g_dv[BB * NN * MM];                 // TRANSPOSED: [(b*NN+n)*MM + m]
__device__ float    g_dpart[BB * MM * CHUNKS * SS];     // per-chunk partial min-over-n
__device__ double   g_part[TAIL_BLOCKS];                // per-tail-block partial sums
__device__ double   g_emb;
__device__ unsigned g_cnt;                              // last-block ticket (self-resetting)

// ---------------- f32x2 packed helpers (sm_100) ----------------
__device__ __forceinline__ ull pk2(float lo, float hi) {
    ull r; asm("mov.b64 %0, {%1, %2};" : "=l"(r) : "f"(lo), "f"(hi)); return r;
}
__device__ __forceinline__ ull fma2(ull a, ull b, ull c) {
    ull r; asm("fma.rn.f32x2 %0, %1, %2, %3;" : "=l"(r) : "l"(a), "l"(b), "l"(c)); return r;
}
__device__ __forceinline__ void upk2(ull v, float& lo, float& hi) {
    asm("mov.b64 {%0, %1}, %2;" : "=f"(lo), "=f"(hi) : "l"(v));
}

__device__ __forceinline__ float fexp_f(float x, float p) {
    float s = (x > 0.f) ? 1.f : ((x < 0.f) ? -1.f : 0.f);
    return s * powf(fabsf(x) + 1e-6f, p);
}

__device__ __forceinline__ double blockReduceSumD(double v) {
    __shared__ double sh[32];
    int lane = threadIdx.x & 31, wid = threadIdx.x >> 5;
    #pragma unroll
    for (int o = 16; o; o >>= 1) v += __shfl_down_sync(0xffffffffu, v, o);
    if (lane == 0) sh[wid] = v;
    __syncthreads();
    int nw = (blockDim.x + 31) >> 5;
    v = (threadIdx.x < nw) ? sh[threadIdx.x] : 0.0;
    if (wid == 0) {
        #pragma unroll
        for (int o = 16; o; o >>= 1) v += __shfl_down_sync(0xffffffffu, v, o);
    }
    __syncthreads();
    return v;
}

// argmax_i emb[b][i][m]  (first max on ties)
__device__ __forceinline__ int argmax_col(const float* __restrict__ emb, int b, int m) {
    int j = 0;
    float best = emb[(b * MM + 0) * MM + m];
    #pragma unroll
    for (int i = 1; i < MM; i++) {
        float v = emb[(b * MM + i) * MM + m];
        if (v > best) { best = v; j = i; }
    }
    return j;
}

// ---------------- kernel 1: fused prep + distance field (+1 emb block) ----------------
// blocks [0, 512):    p2p — per (blkm, chunk), min over S for 256 points -> g_dv (transposed)
// blocks [512, 1024): prim — per (blkm, chunk), partial min over 256 points -> g_dpart
// block 1024:         embeddings regularizer -> g_emb
__global__ void __launch_bounds__(256) k_fused(const float* __restrict__ pcl,
                                               const float* __restrict__ trans,
                                               const float* __restrict__ rot,
                                               const float* __restrict__ size,
                                               const float* __restrict__ shape,
                                               const float* __restrict__ deform,
                                               const float* __restrict__ emb)
{
    int bid = blockIdx.x, t = threadIdx.x;

    if (bid == FUSED_BLOCKS) {
        // ---- embeddings regularizer ----
        double c1 = 0.0, c2 = 0.0, c3 = 0.0;
        if (t < BB * MM) {
            int bb = t / MM, k = t % MM;
            float s1 = 0.f, s2 = 0.f;
            for (int i = 0; i < MM; i++) {
                s1 += emb[(bb * MM + i) * MM + k];
                s2 += emb[(bb * MM + k) * MM + i];
            }
            float d1 = s1 - 1.f, d2 = s2 - 1.f;
            c1 = (double)(d1 * d1);
            c2 = (double)(d2 * d2);
        }
        for (int i = t; i < BB * MM * MM; i += 256) {
            float v = emb[i];
            c3 += (double)(v * (1.f - v));
        }
        double r1 = blockReduceSumD(c1);
        double r2 = blockReduceSumD(c2);
        double r3 = blockReduceSumD(c3);
        if (t == 0)
            g_emb = r1 / (double)(BB * MM) + 10.0 * r2 / (double)(BB * MM)
                  + r3 / (double)(BB * MM * MM);
        return;
    }

    // packed-pair sample points: s_qA[p] = (x0,x1,y0,y1), s_qB[p] = (z0,z1,w0,w1)
    __shared__ float4 s_qA[SS / 2], s_qB[SS / 2];
    __shared__ float4 s_uA[128], s_uB[128];     // prim side: transformed cloud, packed pairs
    __shared__ float  s_R[9], s_t[3], s_par[7];

    int side  = (bid >= P2P_BLOCKS);           // 0 = p2p, 1 = prim
    int pid   = side ? bid - P2P_BLOCKS : bid;
    int blkm  = pid / CHUNKS;
    int chunk = pid % CHUNKS;
    int b     = blkm / MM, m = blkm % MM;

    if (t == 0) {
        int j = argmax_col(emb, b, m);
        const float* q = rot + blkm * 4;
        float w = q[0], x = q[1], y = q[2], z = q[3];
        float inv = rsqrtf(w * w + x * x + y * y + z * z);
        w *= inv; x *= inv; y *= inv; z *= inv;
        s_R[0] = 1.f - 2.f * (y * y + z * z); s_R[1] = 2.f * (x * y - w * z); s_R[2] = 2.f * (x * z + w * y);
        s_R[3] = 2.f * (x * y + w * z); s_R[4] = 1.f - 2.f * (x * x + z * z); s_R[5] = 2.f * (y * z - w * x);
        s_R[6] = 2.f * (x * z - w * y); s_R[7] = 2.f * (y * z + w * x); s_R[8] = 1.f - 2.f * (x * x + y * y);
        s_t[0] = trans[blkm * 3 + 0]; s_t[1] = trans[blkm * 3 + 1]; s_t[2] = trans[blkm * 3 + 2];
        const float* sz3 = size   + (b * MM + j) * 3;
        const float* sh2 = shape  + (b * MM + j) * 2;
        const float* df2 = deform + (b * MM + j) * 2;
        s_par[0] = sh2[0]; s_par[1] = sh2[1];
        s_par[2] = sz3[0]; s_par[3] = sz3[1]; s_par[4] = sz3[2];
        s_par[5] = df2[0]; s_par[6] = df2[1];
    }
    __syncthreads();

    // sample points (all blocks) — written scalar into packed-pair layout
    if (t < SS) {
        float e1 = s_par[0], e2 = s_par[1];
        float sx = s_par[2], sy = s_par[3], szv = s_par[4];
        float dfx = s_par[5], dfy = s_par[6];
        double stepE = (M_PI - 0.1) / (double)(SS - 1);
        double stepO = (2.0 * M_PI - 0.1) / (double)(SS - 1);
        float eta = (float)(-M_PI / 2.0 + 0.05 + t * stepE);
        float omg = (float)(-M_PI + 0.05 + t * stepO);
        float ce = cosf(eta), se = sinf(eta), co = cosf(omg), so = sinf(omg);
        float fce = fexp_f(ce, e1);
        float x = sx * fce * fexp_f(co, e2);
        float y = sy * fce * fexp_f(so, e2);
        float z = szv * fexp_f(se, e1);
        float fx = dfx / szv * z + 1.f;
        float fy = dfy / szv * z + 1.f;
        float X = x * fx, Y = y * fy, Z = z;
        float W = fmaf(X, X, fmaf(Y, Y, Z * Z));
        int p = t >> 1, h = t & 1;
        float* A = (float*)s_qA;  float* Bf = (float*)s_qB;
        A[4 * p + h]     = X;  A[4 * p + 2 + h] = Y;
        Bf[4 * p + h]    = Z;  Bf[4 * p + 2 + h] = W;
    }
    if (side) {
        int n = chunk * 256 + t;
        const float* P = pcl + (b * NN + n) * 3;
        float ax = P[0] - s_t[0], ay = P[1] - s_t[1], az = P[2] - s_t[2];
        float ux = s_R[0] * ax + s_R[1] * ay + s_R[2] * az;
        float uy = s_R[3] * ax + s_R[4] * ay + s_R[5] * az;
        float uz = s_R[6] * ax + s_R[7] * ay + s_R[8] * az;
        float uw = fmaf(ux, ux, fmaf(uy, uy, uz * uz));
        int p = t >> 1, h = t & 1;
        float* A = (float*)s_uA;  float* Bf = (float*)s_uB;
        A[4 * p + h]     = ux; A[4 * p + 2 + h] = uy;
        Bf[4 * p + h]    = uz; Bf[4 * p + 2 + h] = uw;
    }
    __syncthreads();

    if (!side) {
        // ---------- pcl -> prim: min over S (packed f32x2) ----------
        int n = chunk * 256 + t;
        const float* P = pcl + (b * NN + n) * 3;
        float ax = P[0] - s_t[0], ay = P[1] - s_t[1], az = P[2] - s_t[2];
        float tx = s_R[0] * ax + s_R[1] * ay + s_R[2] * az;
        float ty = s_R[3] * ax + s_R[4] * ay + s_R[5] * az;
        float tz = s_R[6] * ax + s_R[7] * ay + s_R[8] * az;
        float tt  = fmaf(tx, tx, fmaf(ty, ty, tz * tz));
        float tx2 = -2.f * tx, ty2 = -2.f * ty, tz2 = -2.f * tz;
        ull tx2p = pk2(tx2, tx2), ty2p = pk2(ty2, ty2), tz2p = pk2(tz2, tz2);

        float m0 = 3.4e38f, m1 = m0, m2 = m0, m3 = m0;
        #pragma unroll 5
        for (int p = 0; p < SS / 2; p += 2) {
            float4 a0 = s_qA[p],     b0 = s_qB[p];
            float4 a1 = s_qA[p + 1], b1 = s_qB[p + 1];
            ull v0 = fma2(pk2(b0.x, b0.y), tz2p, pk2(b0.z, b0.w));
            v0 = fma2(pk2(a0.z, a0.w), ty2p, v0);
            v0 = fma2(pk2(a0.x, a0.y), tx2p, v0);
            float l0, h0; upk2(v0, l0, h0);
            m0 = fminf(m0, l0); m1 = fminf(m1, h0);
            ull v1 = fma2(pk2(b1.x, b1.y), tz2p, pk2(b1.z, b1.w));
            v1 = fma2(pk2(a1.z, a1.w), ty2p, v1);
            v1 = fma2(pk2(a1.x, a1.y), tx2p, v1);
            float l1, h1; upk2(v1, l1, h1);
            m2 = fminf(m2, l1); m3 = fminf(m3, h1);
        }
        float d = fminf(fminf(m0, m1), fminf(m2, m3)) + tt;
        d = fmaxf(d, 0.f);
        g_dv[(b * NN + n) * MM + m] = d;   // transposed store
    } else {
        // ---------- prim -> pcl: partial min over this chunk's 256 points (packed) ----------
        if (t < SS) {
            int p0 = t >> 1, h0i = t & 1;
            const float* A = (const float*)s_qA;  const float* Bf = (const float*)s_qB;
            float qx = A[4 * p0 + h0i], qy = A[4 * p0 + 2 + h0i];
            float qz = Bf[4 * p0 + h0i], qw = Bf[4 * p0 + 2 + h0i];
            float qx2 = -2.f * qx, qy2 = -2.f * qy, qz2 = -2.f * qz;
            ull qx2p = pk2(qx2, qx2), qy2p = pk2(qy2, qy2), qz2p = pk2(qz2, qz2);

            float m0 = 3.4e38f, m1 = m0, m2 = m0, m3 = m0;
            #pragma unroll 4
            for (int p = 0; p < 128; p += 2) {
                float4 a0 = s_uA[p],     b0 = s_uB[p];
                float4 a1 = s_uA[p + 1], b1 = s_uB[p + 1];
                ull v0 = fma2(pk2(b0.x, b0.y), qz2p, pk2(b0.z, b0.w));
                v0 = fma2(pk2(a0.z, a0.w), qy2p, v0);
                v0 = fma2(pk2(a0.x, a0.y), qx2p, v0);
                float l0, h0; upk2(v0, l0, h0);
                m0 = fminf(m0, l0); m1 = fminf(m1, h0);
                ull v1 = fma2(pk2(b1.x, b1.y), qz2p, pk2(b1.z, b1.w));
                v1 = fma2(pk2(a1.z, a1.w), qy2p, v1);
                v1 = fma2(pk2(a1.x, a1.y), qx2p, v1);
                float l1, h1; upk2(v1, l1, h1);
                m2 = fminf(m2, l1); m3 = fminf(m3, h1);
            }
            float d = fminf(fminf(m0, m1), fminf(m2, m3)) + qw;
            d = fmaxf(d, 0.f);
            g_dpart[(blkm * CHUNKS + chunk) * SS + t] = d;
        }
    }
}

// ---------------- kernel 2: tail — p2p weighting, prim reduce, final ----------------
__global__ void __launch_bounds__(256) k_tail(const float* __restrict__ prob,
                                              const float* __restrict__ size,
                                              const float* __restrict__ emb,
                                              float* __restrict__ out)
{
    __shared__ bool s_last;
    int bid = blockIdx.x, t = threadIdx.x;
    double part = 0.0;

    if (bid < TAIL_P2P) {
        // ---- p2p weighting (branch-free stable sort+cumprod equivalent) ----
        __shared__ float s_p[MM];
        int b = bid / CHUNKS, chunk = bid % CHUNKS;
        if (t < MM) s_p[t] = prob[b * MM + t];
        __syncthreads();

        int n = chunk * 256 + t;
        const float4* dvp = (const float4*)&g_dv[(b * NN + n) * MM];
        float4 d0 = dvp[0], d1 = dvp[1], d2 = dvp[2], d3 = dvp[3];
        float dv[MM], pv[MM];
        ((float4*)dv)[0] = d0; ((float4*)dv)[1] = d1;
        ((float4*)dv)[2] = d2; ((float4*)dv)[3] = d3;
        #pragma unroll
        for (int mm = 0; mm < MM; mm++) pv[mm] = s_p[mm];

        float acc = 0.f;
        #pragma unroll
        for (int mm = 0; mm < MM; mm++) {
            float w = pv[mm];
            #pragma unroll
            for (int j = 0; j < MM; j++) {
                if (j == mm) continue;
                bool before = (dv[j] < dv[mm]) || (dv[j] == dv[mm] && j < mm);
                w *= before ? (1.f - pv[j]) : 1.f;
            }
            acc = fmaf(dv[mm], w, acc);
        }
        part = blockReduceSumD((double)acc) / (double)(BB * NN);
    } else {
        // ---- prim partial reduction: 8 blkm per block ----
        int pid = bid - TAIL_P2P;               // 0..7
        int blkm0 = pid * 8;
        int b = blkm0 / MM;
        __shared__ float s_a[MM];
        __shared__ float s_w[8];

        if (t < MM) {
            int j = argmax_col(emb, b, t);
            const float* sz3 = size + (b * MM + j) * 3;
            float a0 = sz3[0], a1 = sz3[1], a2 = sz3[2];
            float ar = powf(a0 * a1, 1.6f) / 3.f + powf(a0 * a2, 1.6f) / 3.f + powf(a1 * a2, 1.6f) / 3.f;
            s_a[t] = 4.f * (float)M_PI * powf(ar, 0.625f);
        }
        __syncthreads();
        if (t < 8) {
            float sa = 0.f;
            #pragma unroll
            for (int mm = 0; mm < MM; mm++) sa += s_a[mm];
            int m_in_b = (blkm0 % MM) + t;
            s_w[t] = s_a[m_in_b] / sa / (float)(SS * BB);
        }
        __syncthreads();

        double acc = 0.0;
        for (int i = t; i < 8 * SS; i += 256) {
            int bl = i / SS, s = i % SS;
            const float* base = g_dpart + ((blkm0 + bl) * CHUNKS) * SS + s;
            float v = base[0];
            #pragma unroll
            for (int c = 1; c < CHUNKS; c++) v = fminf(v, base[c * SS]);
            v = (v >= 1e30f) ? 0.f : v;
            acc += (double)(v * s_w[bl]);
        }
        part = blockReduceSumD(acc);
    }

    if (t == 0) g_part[bid] = part;
    __threadfence();
    if (t == 0) {
        unsigned tk = atomicAdd(&g_cnt, 1u);
        s_last = (tk == (unsigned)(TAIL_BLOCKS - 1));
    }
    __syncthreads();

    if (s_last && t == 0) {
        double p2p = 0.0, prim = 0.0;
        #pragma unroll
        for (int i = 0; i < TAIL_P2P; i++)  p2p  += __ldcg(&g_part[i]);
        #pragma unroll
        for (int i = TAIL_P2P; i < TAIL_BLOCKS; i++) prim += __ldcg(&g_part[i]);
        double embv = __ldcg(&g_emb);
        out[0] = (float)(p2p + prim + embv);
        out[1] = (float)p2p;
        out[2] = (float)prim;
        out[3] = 0.f;
        out[4] = (float)embv;
        g_cnt = 0;   // reset for next graph replay
    }
}

// ---------------- launch ----------------
extern "C" void kernel_launch(void* const* d_in, const int* in_sizes, int n_in,
                              void* d_out, int out_size)
{
    const float* pcl    = (const float*)d_in[0];
    const float* trans  = (const float*)d_in[1];
    const float* rot    = (const float*)d_in[2];
    const float* size   = (const float*)d_in[3];
    const float* shape  = (const float*)d_in[4];
    const float* deform = (const float*)d_in[5];
    const float* prob   = (const float*)d_in[6];
    const float* emb    = (const float*)d_in[7];

    k_fused<<<FUSED_BLOCKS + 1, 256>>>(pcl, trans, rot, size, shape, deform, emb);
    k_tail <<<TAIL_BLOCKS, 256>>>(prob, size, emb, (float*)d_out);
}